// round 1
// baseline (speedup 1.0000x reference)
#include <cuda_runtime.h>
#include <cstdint>

#define PTS     8192
#define NBATCH  4
#define TPB     256
#define NPT     8          // query points per thread (4 packed pairs)
#define NC      4          // PTS / (TPB*NPT)
#define MC      37         // m-chunks
#define MCHUNK  222        // ceil-ish: 37*222 = 8214 >= 8192 (pad with +inf)
#define NBLOCKS (NBATCH * NC * MC)   // 592 = 148 SMs * 4 CTAs

// Scratch: per-point running min of squared distance (float bits; all values >= 0
// so unsigned ordering == float ordering). Init to +inf each run.
__device__ unsigned g_minA[NBATCH * PTS];
__device__ unsigned g_minB[NBATCH * PTS];

#define FMA_F32X2(d, a, b, c) \
    asm("fma.rn.f32x2 %0, %1, %2, %3;" : "=l"(d) : "l"(a), "l"(b), "l"(c))

#define UNPACK_F32X2(lo, hi, v) \
    asm("mov.b64 {%0, %1}, %2;" : "=r"(lo), "=r"(hi) : "l"(v))

__device__ __forceinline__ unsigned long long pack2f(float lo, float hi) {
    unsigned long long r;
    asm("mov.b64 %0, {%1, %2};" : "=l"(r)
        : "r"(__float_as_uint(lo)), "r"(__float_as_uint(hi)));
    return r;
}

__global__ void init_kernel() {
    int i = blockIdx.x * blockDim.x + threadIdx.x;
    if (i < NBATCH * PTS) {
        g_minA[i] = 0x7f800000u;   // +inf
        g_minB[i] = 0x7f800000u;
    }
}

// For each query point n (owned by a thread), compute min over this block's
// m-chunk of (sqb_m + (-2 q_n) . p_m), add sqa_n, clamp at 0, atomicMin into om.
__global__ __launch_bounds__(TPB, 4)
void pass_kernel(const float* __restrict__ Q, const float* __restrict__ P, int dir)
{
    // smem layout per m: {bx,bx,by,by} {bz,bz,s,s}  (lane-duplicated for f32x2)
    __shared__ float4 smv[MCHUNK * 2];

    unsigned* om = dir ? g_minB : g_minA;

    const int bid = blockIdx.x;
    const int mc  = bid % MC;
    const int q16 = bid / MC;      // 0..15
    const int b   = q16 >> 2;
    const int nc  = q16 & 3;
    const int tid = threadIdx.x;

    const float INF = __int_as_float(0x7f800000);

    // ---- fill m-chunk into smem (duplicated lanes), pad tail with +inf ----
    const int mbase = mc * MCHUNK;
    for (int j = tid; j < MCHUNK; j += TPB) {
        int m = mbase + j;
        float bx = 0.f, by = 0.f, bz = 0.f, s = INF;
        if (m < PTS) {
            const float* pp = P + (b * PTS + m) * 3;
            bx = pp[0]; by = pp[1]; bz = pp[2];
            s  = bx * bx + by * by + bz * bz;
        }
        smv[2 * j]     = make_float4(bx, bx, by, by);
        smv[2 * j + 1] = make_float4(bz, bz, s, s);
    }

    // ---- load this thread's 8 query points as 4 packed (-2a) triples ----
    unsigned long long a2x[4], a2y[4], a2z[4];
    float accL[4], accH[4];
    const int nbase = nc * (TPB * NPT);
#pragma unroll
    for (int p = 0; p < 4; ++p) {
        int n0 = nbase + (2 * p) * TPB + tid;
        const float* q0 = Q + (b * PTS + n0) * 3;
        const float* q1 = q0 + TPB * 3;
        a2x[p] = pack2f(-2.f * q0[0], -2.f * q1[0]);
        a2y[p] = pack2f(-2.f * q0[1], -2.f * q1[1]);
        a2z[p] = pack2f(-2.f * q0[2], -2.f * q1[2]);
        accL[p] = INF;
        accH[p] = INF;
    }
    __syncthreads();

    // ---- main loop: 3 FFMA2 + 2 FMNMX per 2 pairs ----
    const ulonglong2* sp = (const ulonglong2*)smv;
#pragma unroll 2
    for (int j = 0; j < MCHUNK; ++j) {
        ulonglong2 w0 = sp[2 * j];        // .x = (bx,bx)  .y = (by,by)
        ulonglong2 w1 = sp[2 * j + 1];    // .x = (bz,bz)  .y = (s, s)
#pragma unroll
        for (int p = 0; p < 4; ++p) {
            unsigned long long t;
            FMA_F32X2(t, a2z[p], w1.x, w1.y);
            FMA_F32X2(t, a2y[p], w0.y, t);
            FMA_F32X2(t, a2x[p], w0.x, t);
            unsigned ulo, uhi;
            UNPACK_F32X2(ulo, uhi, t);
            accL[p] = fminf(accL[p], __uint_as_float(ulo));
            accH[p] = fminf(accH[p], __uint_as_float(uhi));
        }
    }

    // ---- epilogue: add sqa (recomputed from -2a: |a|^2 = 0.25*|a'|^2), clamp, atomicMin
#pragma unroll
    for (int p = 0; p < 4; ++p) {
        unsigned xl, xh, yl, yh, zl, zh;
        UNPACK_F32X2(xl, xh, a2x[p]);
        UNPACK_F32X2(yl, yh, a2y[p]);
        UNPACK_F32X2(zl, zh, a2z[p]);
        float axl = __uint_as_float(xl), axh = __uint_as_float(xh);
        float ayl = __uint_as_float(yl), ayh = __uint_as_float(yh);
        float azl = __uint_as_float(zl), azh = __uint_as_float(zh);
        float sl = 0.25f * (axl * axl + ayl * ayl + azl * azl);
        float sh = 0.25f * (axh * axh + ayh * ayh + azh * azh);
        float dl = fmaxf(accL[p] + sl, 0.f);
        float dh = fmaxf(accH[p] + sh, 0.f);
        int n0 = nbase + (2 * p) * TPB + tid;
        atomicMin(&om[b * PTS + n0],       __float_as_uint(dl));
        atomicMin(&om[b * PTS + n0 + TPB], __float_as_uint(dh));
    }
}

// loss = mean_b(mean_n fwd + mean_m bwd) = (sum(g_minA) + sum(g_minB)) / (B*PTS)
// out  = sqrt(0.5 * loss)
__global__ void reduce_kernel(float* __restrict__ out) {
    const int t = threadIdx.x;
    double s = 0.0;
    for (int i = t; i < NBATCH * PTS; i += 256) {
        s += (double)__uint_as_float(g_minA[i]);
        s += (double)__uint_as_float(g_minB[i]);
    }
    __shared__ double sh[256];
    sh[t] = s;
    __syncthreads();
    for (int o = 128; o > 0; o >>= 1) {
        if (t < o) sh[t] += sh[t + o];
        __syncthreads();
    }
    if (t == 0) {
        double loss = sh[0] / (double)(NBATCH * PTS);
        out[0] = (float)sqrt(0.5 * loss);
    }
}

extern "C" void kernel_launch(void* const* d_in, const int* in_sizes, int n_in,
                              void* d_out, int out_size)
{
    const float* yhat = (const float*)d_in[0];   // [B, N, 3]
    const float* y    = (const float*)d_in[1];   // [B, M, 3]
    (void)in_sizes; (void)n_in; (void)out_size;

    init_kernel<<<32, 1024>>>();
    pass_kernel<<<NBLOCKS, TPB>>>(yhat, y, 0);   // fwd: each yhat point vs all y
    pass_kernel<<<NBLOCKS, TPB>>>(y, yhat, 1);   // bwd: each y point vs all yhat
    reduce_kernel<<<1, 256>>>((float*)d_out);
}

// round 2
// speedup vs baseline: 1.3539x; 1.3539x over previous
#include <cuda_runtime.h>
#include <cstdint>

#define PTS     8192
#define NBATCH  4
#define TPB     256
#define NPT     8          // query points per thread (4 packed pairs)
#define NC      4          // PTS / (TPB*NPT)
#define MC      37         // m-chunks
#define MCHUNK  222        // 37*222 = 8214 >= 8192 (tail padded with +inf)
#define NBLOCKS (NBATCH * NC * MC)   // 592 = 148 SMs * 4 CTAs

// Scratch: per-point running min of squared distance (float bits; all values >= 0
// so unsigned ordering == float ordering). Init to +inf each run.
__device__ unsigned g_minA[NBATCH * PTS];
__device__ unsigned g_minB[NBATCH * PTS];
__device__ float    g_part[64];

#define FMA_F32X2(d, a, b, c) \
    asm("fma.rn.f32x2 %0, %1, %2, %3;" : "=l"(d) : "l"(a), "l"(b), "l"(c))

#define UNPACK_F32X2(lo, hi, v) \
    asm("mov.b64 {%0, %1}, %2;" : "=r"(lo), "=r"(hi) : "l"(v))

__device__ __forceinline__ unsigned long long pack2f(float lo, float hi) {
    unsigned long long r;
    asm("mov.b64 %0, {%1, %2};" : "=l"(r)
        : "r"(__float_as_uint(lo)), "r"(__float_as_uint(hi)));
    return r;
}

__global__ void init_kernel() {
    int i = blockIdx.x * blockDim.x + threadIdx.x;
    if (i < NBATCH * PTS) {
        g_minA[i] = 0x7f800000u;   // +inf
        g_minB[i] = 0x7f800000u;
    }
}

// For each query point n (owned by a thread), compute min over this block's
// m-chunk of (sqb_m + (-2 q_n) . p_m), add sqa_n, clamp at 0, atomicMin into om.
__global__ __launch_bounds__(TPB, 4)
void pass_kernel(const float* __restrict__ Q, const float* __restrict__ P, int dir)
{
    // smem layout per m: {bx,bx,by,by} {bz,bz,s,s}  (lane-duplicated for f32x2)
    __shared__ float4 smv[MCHUNK * 2];

    unsigned* om = dir ? g_minB : g_minA;

    const int bid = blockIdx.x;
    const int mc  = bid % MC;
    const int q16 = bid / MC;      // 0..15
    const int b   = q16 >> 2;
    const int nc  = q16 & 3;
    const int tid = threadIdx.x;

    const float INF = __int_as_float(0x7f800000);

    // ---- fill m-chunk into smem (duplicated lanes), pad tail with +inf ----
    const int mbase = mc * MCHUNK;
    for (int j = tid; j < MCHUNK; j += TPB) {
        int m = mbase + j;
        float bx = 0.f, by = 0.f, bz = 0.f, s = INF;
        if (m < PTS) {
            const float* pp = P + (b * PTS + m) * 3;
            bx = pp[0]; by = pp[1]; bz = pp[2];
            s  = bx * bx + by * by + bz * bz;
        }
        smv[2 * j]     = make_float4(bx, bx, by, by);
        smv[2 * j + 1] = make_float4(bz, bz, s, s);
    }

    // ---- load this thread's 8 query points as 4 packed (-2a) triples ----
    unsigned long long a2x[4], a2y[4], a2z[4];
    float accL[4], accH[4];
    const int nbase = nc * (TPB * NPT);
#pragma unroll
    for (int p = 0; p < 4; ++p) {
        int n0 = nbase + (2 * p) * TPB + tid;
        const float* q0 = Q + (b * PTS + n0) * 3;
        const float* q1 = q0 + TPB * 3;
        a2x[p] = pack2f(-2.f * q0[0], -2.f * q1[0]);
        a2y[p] = pack2f(-2.f * q0[1], -2.f * q1[1]);
        a2z[p] = pack2f(-2.f * q0[2], -2.f * q1[2]);
        accL[p] = INF;
        accH[p] = INF;
    }
    __syncthreads();

    // ---- main loop: 3 FFMA2 + 2 FMNMX per 2 pairs ----
    const ulonglong2* sp = (const ulonglong2*)smv;
#pragma unroll 6
    for (int j = 0; j < MCHUNK; ++j) {
        ulonglong2 w0 = sp[2 * j];        // .x = (bx,bx)  .y = (by,by)
        ulonglong2 w1 = sp[2 * j + 1];    // .x = (bz,bz)  .y = (s, s)
#pragma unroll
        for (int p = 0; p < 4; ++p) {
            unsigned long long t;
            FMA_F32X2(t, a2z[p], w1.x, w1.y);
            FMA_F32X2(t, a2y[p], w0.y, t);
            FMA_F32X2(t, a2x[p], w0.x, t);
            unsigned ulo, uhi;
            UNPACK_F32X2(ulo, uhi, t);
            accL[p] = fminf(accL[p], __uint_as_float(ulo));
            accH[p] = fminf(accH[p], __uint_as_float(uhi));
        }
    }

    // ---- epilogue: add sqa (recomputed from -2a: |a|^2 = 0.25*|a'|^2), clamp, atomicMin
#pragma unroll
    for (int p = 0; p < 4; ++p) {
        unsigned xl, xh, yl, yh, zl, zh;
        UNPACK_F32X2(xl, xh, a2x[p]);
        UNPACK_F32X2(yl, yh, a2y[p]);
        UNPACK_F32X2(zl, zh, a2z[p]);
        float axl = __uint_as_float(xl), axh = __uint_as_float(xh);
        float ayl = __uint_as_float(yl), ayh = __uint_as_float(yh);
        float azl = __uint_as_float(zl), azh = __uint_as_float(zh);
        float sl = 0.25f * (axl * axl + ayl * ayl + azl * azl);
        float sh = 0.25f * (axh * axh + ayh * ayh + azh * azh);
        float dl = fmaxf(accL[p] + sl, 0.f);
        float dh = fmaxf(accH[p] + sh, 0.f);
        int n0 = nbase + (2 * p) * TPB + tid;
        atomicMin(&om[b * PTS + n0],       __float_as_uint(dl));
        atomicMin(&om[b * PTS + n0 + TPB], __float_as_uint(dh));
    }
}

// Stage 1: 64 blocks x 256 threads, each block sums 1024 elements of the
// combined (g_minA ++ g_minB) index space into g_part[blockIdx].
__global__ void reduce_partial_kernel() {
    const int t   = threadIdx.x;
    const int bid = blockIdx.x;
    float s = 0.f;
#pragma unroll
    for (int k = 0; k < 4; ++k) {
        int i = bid * 1024 + k * 256 + t;    // 0 .. 65535
        unsigned v = (i < NBATCH * PTS) ? g_minA[i] : g_minB[i - NBATCH * PTS];
        s += __uint_as_float(v);
    }
    // warp reduce
#pragma unroll
    for (int o = 16; o > 0; o >>= 1)
        s += __shfl_down_sync(0xffffffffu, s, o);
    __shared__ float sh[8];
    if ((t & 31) == 0) sh[t >> 5] = s;
    __syncthreads();
    if (t == 0) {
        float r = 0.f;
#pragma unroll
        for (int w = 0; w < 8; ++w) r += sh[w];
        g_part[bid] = r;
    }
}

// Stage 2: single warp folds the 64 partials; loss -> sqrt(0.5 * mean).
__global__ void reduce_final_kernel(float* __restrict__ out) {
    const int t = threadIdx.x;   // 32 threads
    double s = (double)g_part[t] + (double)g_part[t + 32];
#pragma unroll
    for (int o = 16; o > 0; o >>= 1)
        s += __shfl_down_sync(0xffffffffu, s, o);
    if (t == 0) {
        double loss = s / (double)(NBATCH * PTS);
        out[0] = (float)sqrt(0.5 * loss);
    }
}

extern "C" void kernel_launch(void* const* d_in, const int* in_sizes, int n_in,
                              void* d_out, int out_size)
{
    const float* yhat = (const float*)d_in[0];   // [B, N, 3]
    const float* y    = (const float*)d_in[1];   // [B, M, 3]
    (void)in_sizes; (void)n_in; (void)out_size;

    init_kernel<<<32, 1024>>>();
    pass_kernel<<<NBLOCKS, TPB>>>(yhat, y, 0);   // fwd: each yhat point vs all y
    pass_kernel<<<NBLOCKS, TPB>>>(y, yhat, 1);   // bwd: each y point vs all yhat
    reduce_partial_kernel<<<64, 256>>>();
    reduce_final_kernel<<<1, 32>>>((float*)d_out);
}

// round 3
// speedup vs baseline: 1.3611x; 1.0053x over previous
#include <cuda_runtime.h>
#include <cstdint>

#define PTS     8192
#define NBATCH  4
#define TPB     256
#define NPT     16         // query points per thread (8 packed pairs)
#define NPK     8          // packed f32x2 groups per thread
#define NC      2          // PTS / (TPB*NPT)
#define MC      37         // m-chunks
#define MCHUNK  222        // 37*222 = 8214 >= 8192 (tail padded with +inf)
#define NBLOCKS (NBATCH * NC * MC)   // 296 = 148 SMs * 2 CTAs

// Scratch: per-point running min of squared distance (float bits; all values >= 0
// so unsigned ordering == float ordering). Init to +inf each run.
__device__ unsigned g_minA[NBATCH * PTS];
__device__ unsigned g_minB[NBATCH * PTS];
__device__ float    g_part[64];

#define FMA_F32X2(d, a, b, c) \
    asm("fma.rn.f32x2 %0, %1, %2, %3;" : "=l"(d) : "l"(a), "l"(b), "l"(c))

#define UNPACK_F32X2(lo, hi, v) \
    asm("mov.b64 {%0, %1}, %2;" : "=r"(lo), "=r"(hi) : "l"(v))

__device__ __forceinline__ unsigned long long pack2f(float lo, float hi) {
    unsigned long long r;
    asm("mov.b64 %0, {%1, %2};" : "=l"(r)
        : "r"(__float_as_uint(lo)), "r"(__float_as_uint(hi)));
    return r;
}

__global__ void init_kernel() {
    int i = blockIdx.x * blockDim.x + threadIdx.x;
    if (i < NBATCH * PTS) {
        g_minA[i] = 0x7f800000u;   // +inf
        g_minB[i] = 0x7f800000u;
    }
}

// For each query point n (owned by a thread), compute min over this block's
// m-chunk of (sqb_m + (-2 q_n) . p_m), add sqa_n, clamp at 0, atomicMin into om.
// MLIM = number of m entries this launch processes (MCHUNK for real passes,
// small for the profiling probe; probe is idempotent since a min over a subset
// of m is >= the true min and atomicMin keeps the true min).
template<int MLIM>
__global__ __launch_bounds__(TPB, 2)
void pass_kernel(const float* __restrict__ Q, const float* __restrict__ P, int dir)
{
    // smem layout per m: {bx,bx,by,by} {bz,bz,s,s}  (lane-duplicated for f32x2)
    __shared__ float4 smv[MCHUNK * 2];

    unsigned* om = dir ? g_minB : g_minA;

    const int bid = blockIdx.x;
    const int mc  = bid % MC;
    const int q8  = bid / MC;      // 0..7
    const int b   = q8 >> 1;
    const int nc  = q8 & 1;
    const int tid = threadIdx.x;

    const float INF = __int_as_float(0x7f800000);

    // ---- fill m-chunk into smem (duplicated lanes), pad tail with +inf ----
    const int mbase = mc * MCHUNK;
    for (int j = tid; j < MLIM; j += TPB) {
        int m = mbase + j;
        float bx = 0.f, by = 0.f, bz = 0.f, s = INF;
        if (m < PTS) {
            const float* pp = P + (b * PTS + m) * 3;
            bx = pp[0]; by = pp[1]; bz = pp[2];
            s  = bx * bx + by * by + bz * bz;
        }
        smv[2 * j]     = make_float4(bx, bx, by, by);
        smv[2 * j + 1] = make_float4(bz, bz, s, s);
    }

    // ---- load this thread's 16 query points as 8 packed (-2a) triples ----
    unsigned long long a2x[NPK], a2y[NPK], a2z[NPK];
    float accL[NPK], accH[NPK];
    const int nbase = nc * (TPB * NPT);
#pragma unroll
    for (int p = 0; p < NPK; ++p) {
        int n0 = nbase + (2 * p) * TPB + tid;
        const float* q0 = Q + (b * PTS + n0) * 3;
        const float* q1 = q0 + TPB * 3;
        a2x[p] = pack2f(-2.f * q0[0], -2.f * q1[0]);
        a2y[p] = pack2f(-2.f * q0[1], -2.f * q1[1]);
        a2z[p] = pack2f(-2.f * q0[2], -2.f * q1[2]);
        accL[p] = INF;
        accH[p] = INF;
    }
    __syncthreads();

    // ---- main loop: 3 FFMA2 + 2 FMNMX per 2 pairs ----
    const ulonglong2* sp = (const ulonglong2*)smv;
#pragma unroll 3
    for (int j = 0; j < MLIM; ++j) {
        ulonglong2 w0 = sp[2 * j];        // .x = (bx,bx)  .y = (by,by)
        ulonglong2 w1 = sp[2 * j + 1];    // .x = (bz,bz)  .y = (s, s)
#pragma unroll
        for (int p = 0; p < NPK; ++p) {
            unsigned long long t;
            FMA_F32X2(t, a2z[p], w1.x, w1.y);
            FMA_F32X2(t, a2y[p], w0.y, t);
            FMA_F32X2(t, a2x[p], w0.x, t);
            unsigned ulo, uhi;
            UNPACK_F32X2(ulo, uhi, t);
            accL[p] = fminf(accL[p], __uint_as_float(ulo));
            accH[p] = fminf(accH[p], __uint_as_float(uhi));
        }
    }

    // ---- epilogue: add sqa (recomputed from -2a: |a|^2 = 0.25*|a'|^2), clamp, atomicMin
#pragma unroll
    for (int p = 0; p < NPK; ++p) {
        unsigned xl, xh, yl, yh, zl, zh;
        UNPACK_F32X2(xl, xh, a2x[p]);
        UNPACK_F32X2(yl, yh, a2y[p]);
        UNPACK_F32X2(zl, zh, a2z[p]);
        float axl = __uint_as_float(xl), axh = __uint_as_float(xh);
        float ayl = __uint_as_float(yl), ayh = __uint_as_float(yh);
        float azl = __uint_as_float(zl), azh = __uint_as_float(zh);
        float sl = 0.25f * (axl * axl + ayl * ayl + azl * azl);
        float sh = 0.25f * (axh * axh + ayh * ayh + azh * azh);
        float dl = fmaxf(accL[p] + sl, 0.f);
        float dh = fmaxf(accH[p] + sh, 0.f);
        int n0 = nbase + (2 * p) * TPB + tid;
        atomicMin(&om[b * PTS + n0],       __float_as_uint(dl));
        atomicMin(&om[b * PTS + n0 + TPB], __float_as_uint(dh));
    }
}

// Stage 1: 64 blocks x 256 threads, each block sums 1024 elements of the
// combined (g_minA ++ g_minB) index space into g_part[blockIdx].
__global__ void reduce_partial_kernel() {
    const int t   = threadIdx.x;
    const int bid = blockIdx.x;
    float s = 0.f;
#pragma unroll
    for (int k = 0; k < 4; ++k) {
        int i = bid * 1024 + k * 256 + t;    // 0 .. 65535
        unsigned v = (i < NBATCH * PTS) ? g_minA[i] : g_minB[i - NBATCH * PTS];
        s += __uint_as_float(v);
    }
#pragma unroll
    for (int o = 16; o > 0; o >>= 1)
        s += __shfl_down_sync(0xffffffffu, s, o);
    __shared__ float sh[8];
    if ((t & 31) == 0) sh[t >> 5] = s;
    __syncthreads();
    if (t == 0) {
        float r = 0.f;
#pragma unroll
        for (int w = 0; w < 8; ++w) r += sh[w];
        g_part[bid] = r;
    }
}

// Stage 2: single warp folds the 64 partials; loss -> sqrt(0.5 * mean).
__global__ void reduce_final_kernel(float* __restrict__ out) {
    const int t = threadIdx.x;   // 32 threads
    double s = (double)g_part[t] + (double)g_part[t + 32];
#pragma unroll
    for (int o = 16; o > 0; o >>= 1)
        s += __shfl_down_sync(0xffffffffu, s, o);
    if (t == 0) {
        double loss = s / (double)(NBATCH * PTS);
        out[0] = (float)sqrt(0.5 * loss);
    }
}

extern "C" void kernel_launch(void* const* d_in, const int* in_sizes, int n_in,
                              void* d_out, int out_size)
{
    const float* yhat = (const float*)d_in[0];   // [B, N, 3]
    const float* y    = (const float*)d_in[1];   // [B, M, 3]
    (void)in_sizes; (void)n_in; (void)out_size;

    init_kernel<<<32, 1024>>>();
    pass_kernel<MCHUNK><<<NBLOCKS, TPB>>>(yhat, y, 0);   // fwd
    pass_kernel<MCHUNK><<<NBLOCKS, TPB>>>(y, yhat, 1);   // bwd
    // Profiling probe (launch #4): same inner loop, 16 blocks (mc=0 only),
    // 96 m-iters. Idempotent w.r.t. atomicMin; costs ~2us.
    pass_kernel<96><<<NBATCH * NC, TPB>>>(y, yhat, 1);
    reduce_partial_kernel<<<64, 256>>>();
    reduce_final_kernel<<<1, 32>>>((float*)d_out);
}